// round 3
// baseline (speedup 1.0000x reference)
#include <cuda_runtime.h>
#include <math.h>

#define B_   2
#define L_   2048
#define D_   1024
#define H_   16
#define DK_  64
#define QKVN (3 * D_)
#define SOFTMAX_SCALE 0.125f   // 1/sqrt(64)

// Scratch (allocation-free): qkv projection and attention output
__device__ float g_qkv [(size_t)B_ * L_ * QKVN];   // [B*L, 3072]
__device__ float g_attn[(size_t)B_ * L_ * D_];     // [B*L, 1024]

// ---------------------------------------------------------------------------
// GEMM: C[M,N] = A[M,K] @ W[K,N] + bias[N]   (all row-major, fp32)
// 128x128 block, BK=16, 256 threads, 8x8 microtile (4+4 split for
// conflict-free smem float4 reads).
// Requires M%128==0, N%128==0, K%16==0 (true for all our shapes).
// ---------------------------------------------------------------------------
__global__ __launch_bounds__(256, 2) void sgemm_bias_kernel(
    const float* __restrict__ A, const float* __restrict__ W,
    const float* __restrict__ bias, float* __restrict__ C,
    int M, int N, int K)
{
    __shared__ float As[16][132];   // k-major, transposed A tile
    __shared__ float Ws[16][128];   // natural W tile

    const int t  = threadIdx.x;
    const int ty = t >> 4;          // 0..15 -> row group
    const int tx = t & 15;          // 0..15 -> col group
    const int m0 = blockIdx.y * 128;
    const int n0 = blockIdx.x * 128;

    float acc[8][8];
#pragma unroll
    for (int i = 0; i < 8; i++)
#pragma unroll
        for (int j = 0; j < 8; j++) acc[i][j] = 0.0f;

    for (int k0 = 0; k0 < K; k0 += 16) {
        // Load A tile (128 rows x 16 k): 512 float4, 2 per thread, store transposed
#pragma unroll
        for (int i = 0; i < 2; i++) {
            int li  = t + 256 * i;
            int row = li >> 2;
            int kq  = (li & 3) << 2;
            float4 v = *(const float4*)(A + (size_t)(m0 + row) * K + k0 + kq);
            As[kq + 0][row] = v.x;
            As[kq + 1][row] = v.y;
            As[kq + 2][row] = v.z;
            As[kq + 3][row] = v.w;
        }
        // Load W tile (16 k x 128 n): 512 float4, 2 per thread, natural layout
#pragma unroll
        for (int i = 0; i < 2; i++) {
            int li = t + 256 * i;
            int kr = li >> 5;
            int nq = (li & 31) << 2;
            *(float4*)(&Ws[kr][nq]) =
                *(const float4*)(W + (size_t)(k0 + kr) * N + n0 + nq);
        }
        __syncthreads();

#pragma unroll
        for (int kk = 0; kk < 16; kk++) {
            float a[8], b[8];
            *(float4*)&a[0] = *(float4*)&As[kk][ty * 4];
            *(float4*)&a[4] = *(float4*)&As[kk][ty * 4 + 64];
            *(float4*)&b[0] = *(float4*)&Ws[kk][tx * 4];
            *(float4*)&b[4] = *(float4*)&Ws[kk][tx * 4 + 64];
#pragma unroll
            for (int ii = 0; ii < 8; ii++)
#pragma unroll
                for (int jj = 0; jj < 8; jj++)
                    acc[ii][jj] = fmaf(a[ii], b[jj], acc[ii][jj]);
        }
        __syncthreads();
    }

    float4 bz0 = *(const float4*)(bias + n0 + tx * 4);
    float4 bz1 = *(const float4*)(bias + n0 + 64 + tx * 4);
#pragma unroll
    for (int ii = 0; ii < 8; ii++) {
        int r = m0 + ty * 4 + ((ii < 4) ? ii : 64 + ii - 4);
        float4 c0 = make_float4(acc[ii][0] + bz0.x, acc[ii][1] + bz0.y,
                                acc[ii][2] + bz0.z, acc[ii][3] + bz0.w);
        float4 c1 = make_float4(acc[ii][4] + bz1.x, acc[ii][5] + bz1.y,
                                acc[ii][6] + bz1.z, acc[ii][7] + bz1.w);
        *(float4*)(C + (size_t)r * N + n0 + tx * 4)      = c0;
        *(float4*)(C + (size_t)r * N + n0 + 64 + tx * 4) = c1;
    }
}

// ---------------------------------------------------------------------------
// Flash attention (fp32): one block = (batch b, head h, 128-row Q tile).
// KV tile = 64 rows. Online softmax; S and O accumulators in registers.
// Thread layout 16x16: thread (ty,tx) owns Q rows {ty*4+i, ty*4+64+i} and
// 4 columns {tx*4+j} of S / of the head dim for O.
// smem (dynamic, 100 KB): Qs[64][132] k-major, Ks[64][68] k-major,
//                         Vs[64][68] natural, Ps[64][132] j-major.
// ---------------------------------------------------------------------------
#define QS_OFF 0
#define KS_OFF (64 * 132)
#define VS_OFF (KS_OFF + 64 * 68)
#define PS_OFF (VS_OFF + 64 * 68)
#define FLASH_SMEM ((PS_OFF + 64 * 132) * 4)

__global__ __launch_bounds__(256, 2) void flash_kernel(
    const float* __restrict__ qkv, float* __restrict__ attn_out)
{
    extern __shared__ float sm[];
    float* Qs = sm + QS_OFF;
    float* Ks = sm + KS_OFF;
    float* Vs = sm + VS_OFF;
    float* Ps = sm + PS_OFF;

    const int t  = threadIdx.x;
    const int ty = t >> 4;
    const int tx = t & 15;
    const int q0 = blockIdx.x * 128;
    const int h  = blockIdx.y;
    const int b  = blockIdx.z;

    const float* basep = qkv + (size_t)b * L_ * QKVN + h * (3 * DK_);

    // Load Q tile (128 x 64) transposed into Qs[k][r]
#pragma unroll
    for (int i = 0; i < 8; i++) {
        int li  = t + 256 * i;
        int row = li >> 4;
        int kq  = (li & 15) << 2;
        float4 v = *(const float4*)(basep + (size_t)(q0 + row) * QKVN + kq);
        Qs[(kq + 0) * 132 + row] = v.x;
        Qs[(kq + 1) * 132 + row] = v.y;
        Qs[(kq + 2) * 132 + row] = v.z;
        Qs[(kq + 3) * 132 + row] = v.w;
    }

    float m[8], l[8], o[8][4];
#pragma unroll
    for (int i = 0; i < 8; i++) {
        m[i] = -1e30f;
        l[i] = 0.0f;
#pragma unroll
        for (int j = 0; j < 4; j++) o[i][j] = 0.0f;
    }

    for (int kt = 0; kt < L_ / 64; kt++) {
        __syncthreads();   // previous iteration's PV readers done
        const int kv0 = kt * 64;
        // Load K tile (transposed) and V tile (natural)
#pragma unroll
        for (int i = 0; i < 4; i++) {
            int li  = t + 256 * i;
            int row = li >> 4;
            int kq  = (li & 15) << 2;
            const float* src = basep + (size_t)(kv0 + row) * QKVN;
            float4 kv = *(const float4*)(src + DK_ + kq);
            Ks[(kq + 0) * 68 + row] = kv.x;
            Ks[(kq + 1) * 68 + row] = kv.y;
            Ks[(kq + 2) * 68 + row] = kv.z;
            Ks[(kq + 3) * 68 + row] = kv.w;
            float4 vv = *(const float4*)(src + 2 * DK_ + kq);
            *(float4*)(Vs + row * 68 + kq) = vv;
        }
        __syncthreads();

        // S = Q K^T  (8 rows x 4 cols per thread)
        float s[8][4];
#pragma unroll
        for (int i = 0; i < 8; i++)
#pragma unroll
            for (int j = 0; j < 4; j++) s[i][j] = 0.0f;

#pragma unroll 4
        for (int k = 0; k < 64; k++) {
            float4 a0 = *(float4*)(Qs + k * 132 + ty * 4);
            float4 a1 = *(float4*)(Qs + k * 132 + ty * 4 + 64);
            float4 bk = *(float4*)(Ks + k * 68 + tx * 4);
            float av[8] = {a0.x, a0.y, a0.z, a0.w, a1.x, a1.y, a1.z, a1.w};
            float bv[4] = {bk.x, bk.y, bk.z, bk.w};
#pragma unroll
            for (int ii = 0; ii < 8; ii++)
#pragma unroll
                for (int jj = 0; jj < 4; jj++)
                    s[ii][jj] = fmaf(av[ii], bv[jj], s[ii][jj]);
        }

        // Online softmax per row (row spread across the 16 tx lanes of a group)
#pragma unroll
        for (int i = 0; i < 8; i++) {
#pragma unroll
            for (int j = 0; j < 4; j++) s[i][j] *= SOFTMAX_SCALE;
            float rmax = fmaxf(fmaxf(s[i][0], s[i][1]), fmaxf(s[i][2], s[i][3]));
#pragma unroll
            for (int off = 8; off > 0; off >>= 1)
                rmax = fmaxf(rmax, __shfl_xor_sync(0xffffffffu, rmax, off));
            float mn   = fmaxf(m[i], rmax);
            float corr = __expf(m[i] - mn);
            m[i] = mn;
            l[i] *= corr;
#pragma unroll
            for (int j = 0; j < 4; j++) o[i][j] *= corr;
            float rs = 0.0f;
#pragma unroll
            for (int j = 0; j < 4; j++) {
                float p = __expf(s[i][j] - mn);
                s[i][j] = p;
                rs += p;
            }
#pragma unroll
            for (int off = 8; off > 0; off >>= 1)
                rs += __shfl_xor_sync(0xffffffffu, rs, off);
            l[i] += rs;
            int r = ty * 4 + ((i < 4) ? i : 64 + i - 4);
#pragma unroll
            for (int j = 0; j < 4; j++)
                Ps[(tx * 4 + j) * 132 + r] = s[i][j];
        }
        __syncthreads();

        // O += P V
#pragma unroll 4
        for (int k = 0; k < 64; k++) {
            float4 a0 = *(float4*)(Ps + k * 132 + ty * 4);
            float4 a1 = *(float4*)(Ps + k * 132 + ty * 4 + 64);
            float4 bv = *(float4*)(Vs + k * 68 + tx * 4);
            float av[8] = {a0.x, a0.y, a0.z, a0.w, a1.x, a1.y, a1.z, a1.w};
            float vv[4] = {bv.x, bv.y, bv.z, bv.w};
#pragma unroll
            for (int ii = 0; ii < 8; ii++)
#pragma unroll
                for (int jj = 0; jj < 4; jj++)
                    o[ii][jj] = fmaf(av[ii], vv[jj], o[ii][jj]);
        }
    }

    // Epilogue: normalize and write to [B, L, D] layout (head-merged)
#pragma unroll
    for (int i = 0; i < 8; i++) {
        int r = q0 + ty * 4 + ((i < 4) ? i : 64 + i - 4);
        float inv = 1.0f / l[i];
        float4 ov = make_float4(o[i][0] * inv, o[i][1] * inv,
                                o[i][2] * inv, o[i][3] * inv);
        *(float4*)(attn_out + ((size_t)b * L_ + r) * D_ + h * DK_ + tx * 4) = ov;
    }
}

// ---------------------------------------------------------------------------
// Launch
// ---------------------------------------------------------------------------
extern "C" void kernel_launch(void* const* d_in, const int* in_sizes, int n_in,
                              void* d_out, int out_size)
{
    const float* x     = (const float*)d_in[0];
    const float* w_qkv = (const float*)d_in[1];
    const float* b_qkv = (const float*)d_in[2];
    const float* w_out = (const float*)d_in[3];
    const float* b_out = (const float*)d_in[4];
    float* out = (float*)d_out;

    void *p0, *p1;
    cudaGetSymbolAddress(&p0, g_qkv);
    cudaGetSymbolAddress(&p1, g_attn);
    float* qkv  = (float*)p0;
    float* attn = (float*)p1;

    const int M = B_ * L_;   // 4096

    // 1) QKV projection: [4096,1024] @ [1024,3072] + b_qkv
    sgemm_bias_kernel<<<dim3(QKVN / 128, M / 128), 256>>>(
        x, w_qkv, b_qkv, qkv, M, QKVN, D_);

    // 2) Flash attention per (q-tile, head, batch)
    cudaFuncSetAttribute(flash_kernel,
                         cudaFuncAttributeMaxDynamicSharedMemorySize, FLASH_SMEM);
    flash_kernel<<<dim3(L_ / 128, H_, B_), 256, FLASH_SMEM>>>(qkv, attn);

    // 3) Output projection: [4096,1024] @ [1024,1024] + b_out
    sgemm_bias_kernel<<<dim3(D_ / 128, M / 128), 256>>>(
        attn, w_out, b_out, out, M, D_, D_);
}

// round 5
// speedup vs baseline: 1.3363x; 1.3363x over previous
#include <cuda_runtime.h>
#include <cstdint>
#include <math.h>

#define B_   2
#define L_   2048
#define D_   1024
#define H_   16
#define DK_  64
#define QKVN (3 * D_)
#define SOFTMAX_SCALE 0.125f   // 1/sqrt(64)

// Scratch (allocation-free)
__device__ float g_qkv  [(size_t)B_ * L_ * QKVN];   // [B*L, 3072]
__device__ float g_attn [(size_t)B_ * L_ * D_];     // [B*L, 1024]
__device__ float g_wqkvt[(size_t)QKVN * D_];        // W_qkv^T  [3072,1024]
__device__ float g_woutt[(size_t)D_ * D_];          // W_out^T  [1024,1024]

// ---------------------------------------------------------------------------
// helpers
// ---------------------------------------------------------------------------
__device__ __forceinline__ uint32_t f2tf(float f) {   // fp32 -> tf32 (rna)
    uint32_t u;
    asm("cvt.rna.tf32.f32 %0, %1;" : "=r"(u) : "f"(f));
    return u;
}

// m16n8k8 tf32 HMMA (sm_80+ portable path; compiles on plain sm_103 target)
__device__ __forceinline__ void mma_tf32(float c[4],
                                         uint32_t a0, uint32_t a1,
                                         uint32_t a2, uint32_t a3,
                                         uint32_t b0, uint32_t b1)
{
    asm volatile(
        "mma.sync.aligned.m16n8k8.row.col.f32.tf32.tf32.f32 "
        "{%0,%1,%2,%3}, {%4,%5,%6,%7}, {%8,%9}, {%0,%1,%2,%3};"
        : "+f"(c[0]), "+f"(c[1]), "+f"(c[2]), "+f"(c[3])
        : "r"(a0), "r"(a1), "r"(a2), "r"(a3), "r"(b0), "r"(b1));
}

// ---------------------------------------------------------------------------
// Transpose: src [R,C] -> dst [C,R]   (R,C multiples of 32)
// ---------------------------------------------------------------------------
__global__ void transpose_kernel(const float* __restrict__ src,
                                 float* __restrict__ dst, int R, int C)
{
    __shared__ float tile[32][33];
    int c0 = blockIdx.x * 32, r0 = blockIdx.y * 32;
    int x = threadIdx.x, y = threadIdx.y;
#pragma unroll
    for (int i = 0; i < 32; i += 8)
        tile[y + i][x] = src[(size_t)(r0 + y + i) * C + c0 + x];
    __syncthreads();
#pragma unroll
    for (int i = 0; i < 32; i += 8)
        dst[(size_t)(c0 + y + i) * R + r0 + x] = tile[x][y + i];
}

// ---------------------------------------------------------------------------
// Tensor-core GEMM (mma.sync tf32): C[M,N] = A[M,K] @ Bt[N,K]^T + bias[N]
// Block tile 128x128, 8 warps (2m x 4n), warp tile 64x32, BK=32.
// Double-buffered smem, register-staged gmem prefetch, 1 sync per chunk.
// smem layout: pad-36 rows -> all fragment LDS conflict-free.
// M,N multiples of 128; K multiple of 32.
// ---------------------------------------------------------------------------
#define PAD    36
#define TILE_F (128 * PAD)                 // floats per operand per stage
#define GM_SMEM (4 * TILE_F * 4)           // 2 stages x (A+B) = 73728 B

__global__ __launch_bounds__(256) void gemm_mma_kernel(
    const float* __restrict__ A, const float* __restrict__ Bt,
    const float* __restrict__ bias, float* __restrict__ C,
    int M, int N, int K)
{
    extern __shared__ float smf[];
    float* As = smf;                 // [2][TILE_F]
    float* Bs = smf + 2 * TILE_F;    // [2][TILE_F]

    const int t    = threadIdx.x;
    const int lane = t & 31;
    const int wid  = t >> 5;
    const int wm   = wid & 1;        // 0..1 -> 64-row slab
    const int wn   = wid >> 1;       // 0..3 -> 32-col slab
    const int m0   = blockIdx.y * 128;
    const int n0   = blockIdx.x * 128;
    const int g    = lane >> 2;      // group id 0..7
    const int tg   = lane & 3;       // thread-in-group 0..3

    float c[4][4][4];
#pragma unroll
    for (int i = 0; i < 4; i++)
#pragma unroll
        for (int j = 0; j < 4; j++)
#pragma unroll
            for (int x = 0; x < 4; x++) c[i][j][x] = 0.0f;

    const int nchunks = K >> 5;      // BK = 32
    float4 ra[4], rb[4];

    // prologue: load chunk 0 -> regs -> smem stage 0
#pragma unroll
    for (int it = 0; it < 4; it++) {
        int li = t + 256 * it;
        int r  = li >> 3;
        int kq = (li & 7) << 2;
        ra[it] = *(const float4*)(A  + (size_t)(m0 + r) * K + kq);
        rb[it] = *(const float4*)(Bt + (size_t)(n0 + r) * K + kq);
    }
#pragma unroll
    for (int it = 0; it < 4; it++) {
        int li = t + 256 * it;
        int r  = li >> 3;
        int kq = (li & 7) << 2;
        *(uint4*)(As + r * PAD + kq) =
            make_uint4(f2tf(ra[it].x), f2tf(ra[it].y), f2tf(ra[it].z), f2tf(ra[it].w));
        *(uint4*)(Bs + r * PAD + kq) =
            make_uint4(f2tf(rb[it].x), f2tf(rb[it].y), f2tf(rb[it].z), f2tf(rb[it].w));
    }
    __syncthreads();

    for (int kt = 0; kt < nchunks; kt++) {
        const int buf = kt & 1;
        const bool more = (kt + 1 < nchunks);

        if (more) {
            const int k0 = (kt + 1) << 5;
#pragma unroll
            for (int it = 0; it < 4; it++) {
                int li = t + 256 * it;
                int r  = li >> 3;
                int kq = (li & 7) << 2;
                ra[it] = *(const float4*)(A  + (size_t)(m0 + r) * K + k0 + kq);
                rb[it] = *(const float4*)(Bt + (size_t)(n0 + r) * K + k0 + kq);
            }
        }

        // compute current stage: 4 k-steps of 8
        const float* pa0 = As + buf * TILE_F + (wm * 64 + g) * PAD + tg;
        const float* pb0 = Bs + buf * TILE_F + (wn * 32 + g) * PAD + tg;
#pragma unroll
        for (int ks = 0; ks < 4; ks++) {
            const float* pa = pa0 + ks * 8;
            const float* pb = pb0 + ks * 8;
            uint32_t a[4][4], b[4][2];
#pragma unroll
            for (int i = 0; i < 4; i++) {
                a[i][0] = __float_as_uint(pa[(i * 16    ) * PAD    ]);
                a[i][1] = __float_as_uint(pa[(i * 16 + 8) * PAD    ]);
                a[i][2] = __float_as_uint(pa[(i * 16    ) * PAD + 4]);
                a[i][3] = __float_as_uint(pa[(i * 16 + 8) * PAD + 4]);
            }
#pragma unroll
            for (int j = 0; j < 4; j++) {
                b[j][0] = __float_as_uint(pb[(j * 8) * PAD    ]);
                b[j][1] = __float_as_uint(pb[(j * 8) * PAD + 4]);
            }
#pragma unroll
            for (int i = 0; i < 4; i++)
#pragma unroll
                for (int j = 0; j < 4; j++)
                    mma_tf32(c[i][j], a[i][0], a[i][1], a[i][2], a[i][3],
                             b[j][0], b[j][1]);
        }

        if (more) {
#pragma unroll
            for (int it = 0; it < 4; it++) {
                int li = t + 256 * it;
                int r  = li >> 3;
                int kq = (li & 7) << 2;
                *(uint4*)(As + (buf ^ 1) * TILE_F + r * PAD + kq) =
                    make_uint4(f2tf(ra[it].x), f2tf(ra[it].y),
                               f2tf(ra[it].z), f2tf(ra[it].w));
                *(uint4*)(Bs + (buf ^ 1) * TILE_F + r * PAD + kq) =
                    make_uint4(f2tf(rb[it].x), f2tf(rb[it].y),
                               f2tf(rb[it].z), f2tf(rb[it].w));
            }
        }
        __syncthreads();
    }

    // epilogue: C fragment layout -> gmem (+bias), float2 stores
    const int ncol0 = n0 + wn * 32;
#pragma unroll
    for (int j = 0; j < 4; j++) {
        int cb = j * 8 + 2 * tg;
        float bv0 = bias[ncol0 + cb];
        float bv1 = bias[ncol0 + cb + 1];
#pragma unroll
        for (int i = 0; i < 4; i++) {
            int r = m0 + wm * 64 + i * 16 + g;
            float2 v0 = make_float2(c[i][j][0] + bv0, c[i][j][1] + bv1);
            float2 v1 = make_float2(c[i][j][2] + bv0, c[i][j][3] + bv1);
            *(float2*)(C + (size_t)r * N + ncol0 + cb)       = v0;
            *(float2*)(C + (size_t)(r + 8) * N + ncol0 + cb) = v1;
        }
    }
}

// ===========================================================================
// Flash attention (fp32) — unchanged (validated, rel_err 1.4e-6)
// ===========================================================================
#define QS_OFF 0
#define KS_OFF (64 * 132)
#define VS_OFF (KS_OFF + 64 * 68)
#define PS_OFF (VS_OFF + 64 * 68)
#define FLASH_SMEM ((PS_OFF + 64 * 132) * 4)

__global__ __launch_bounds__(256, 2) void flash_kernel(
    const float* __restrict__ qkv, float* __restrict__ attn_out)
{
    extern __shared__ float smf[];
    float* Qs = smf + QS_OFF;
    float* Ks = smf + KS_OFF;
    float* Vs = smf + VS_OFF;
    float* Ps = smf + PS_OFF;

    const int t  = threadIdx.x;
    const int ty = t >> 4;
    const int tx = t & 15;
    const int q0 = blockIdx.x * 128;
    const int h  = blockIdx.y;
    const int b  = blockIdx.z;

    const float* basep = qkv + (size_t)b * L_ * QKVN + h * (3 * DK_);

#pragma unroll
    for (int i = 0; i < 8; i++) {
        int li  = t + 256 * i;
        int row = li >> 4;
        int kq  = (li & 15) << 2;
        float4 v = *(const float4*)(basep + (size_t)(q0 + row) * QKVN + kq);
        Qs[(kq + 0) * 132 + row] = v.x;
        Qs[(kq + 1) * 132 + row] = v.y;
        Qs[(kq + 2) * 132 + row] = v.z;
        Qs[(kq + 3) * 132 + row] = v.w;
    }

    float m[8], l[8], o[8][4];
#pragma unroll
    for (int i = 0; i < 8; i++) {
        m[i] = -1e30f; l[i] = 0.0f;
#pragma unroll
        for (int j = 0; j < 4; j++) o[i][j] = 0.0f;
    }

    for (int kt = 0; kt < L_ / 64; kt++) {
        __syncthreads();
        const int kv0 = kt * 64;
#pragma unroll
        for (int i = 0; i < 4; i++) {
            int li  = t + 256 * i;
            int row = li >> 4;
            int kq  = (li & 15) << 2;
            const float* src = basep + (size_t)(kv0 + row) * QKVN;
            float4 kv = *(const float4*)(src + DK_ + kq);
            Ks[(kq + 0) * 68 + row] = kv.x;
            Ks[(kq + 1) * 68 + row] = kv.y;
            Ks[(kq + 2) * 68 + row] = kv.z;
            Ks[(kq + 3) * 68 + row] = kv.w;
            float4 vv = *(const float4*)(src + 2 * DK_ + kq);
            *(float4*)(Vs + row * 68 + kq) = vv;
        }
        __syncthreads();

        float s[8][4];
#pragma unroll
        for (int i = 0; i < 8; i++)
#pragma unroll
            for (int j = 0; j < 4; j++) s[i][j] = 0.0f;

#pragma unroll 4
        for (int k = 0; k < 64; k++) {
            float4 a0 = *(float4*)(Qs + k * 132 + ty * 4);
            float4 a1 = *(float4*)(Qs + k * 132 + ty * 4 + 64);
            float4 bk = *(float4*)(Ks + k * 68 + tx * 4);
            float av[8] = {a0.x, a0.y, a0.z, a0.w, a1.x, a1.y, a1.z, a1.w};
            float bv[4] = {bk.x, bk.y, bk.z, bk.w};
#pragma unroll
            for (int ii = 0; ii < 8; ii++)
#pragma unroll
                for (int jj = 0; jj < 4; jj++)
                    s[ii][jj] = fmaf(av[ii], bv[jj], s[ii][jj]);
        }

#pragma unroll
        for (int i = 0; i < 8; i++) {
#pragma unroll
            for (int j = 0; j < 4; j++) s[i][j] *= SOFTMAX_SCALE;
            float rmax = fmaxf(fmaxf(s[i][0], s[i][1]), fmaxf(s[i][2], s[i][3]));
#pragma unroll
            for (int off = 8; off > 0; off >>= 1)
                rmax = fmaxf(rmax, __shfl_xor_sync(0xffffffffu, rmax, off));
            float mn   = fmaxf(m[i], rmax);
            float corr = __expf(m[i] - mn);
            m[i] = mn;
            l[i] *= corr;
#pragma unroll
            for (int j = 0; j < 4; j++) o[i][j] *= corr;
            float rs = 0.0f;
#pragma unroll
            for (int j = 0; j < 4; j++) {
                float p = __expf(s[i][j] - mn);
                s[i][j] = p;
                rs += p;
            }
#pragma unroll
            for (int off = 8; off > 0; off >>= 1)
                rs += __shfl_xor_sync(0xffffffffu, rs, off);
            l[i] += rs;
            int r = ty * 4 + ((i < 4) ? i : 64 + i - 4);
#pragma unroll
            for (int j = 0; j < 4; j++)
                Ps[(tx * 4 + j) * 132 + r] = s[i][j];
        }
        __syncthreads();

#pragma unroll 4
        for (int k = 0; k < 64; k++) {
            float4 a0 = *(float4*)(Ps + k * 132 + ty * 4);
            float4 a1 = *(float4*)(Ps + k * 132 + ty * 4 + 64);
            float4 bv = *(float4*)(Vs + k * 68 + tx * 4);
            float av[8] = {a0.x, a0.y, a0.z, a0.w, a1.x, a1.y, a1.z, a1.w};
            float vv[4] = {bv.x, bv.y, bv.z, bv.w};
#pragma unroll
            for (int ii = 0; ii < 8; ii++)
#pragma unroll
                for (int jj = 0; jj < 4; jj++)
                    o[ii][jj] = fmaf(av[ii], vv[jj], o[ii][jj]);
        }
    }

#pragma unroll
    for (int i = 0; i < 8; i++) {
        int r = q0 + ty * 4 + ((i < 4) ? i : 64 + i - 4);
        float inv = 1.0f / l[i];
        float4 ov = make_float4(o[i][0] * inv, o[i][1] * inv,
                                o[i][2] * inv, o[i][3] * inv);
        *(float4*)(attn_out + ((size_t)b * L_ + r) * D_ + h * DK_ + tx * 4) = ov;
    }
}

// ===========================================================================
// Launch
// ===========================================================================
extern "C" void kernel_launch(void* const* d_in, const int* in_sizes, int n_in,
                              void* d_out, int out_size)
{
    const float* x     = (const float*)d_in[0];
    const float* w_qkv = (const float*)d_in[1];
    const float* b_qkv = (const float*)d_in[2];
    const float* w_out = (const float*)d_in[3];
    const float* b_out = (const float*)d_in[4];
    float* out = (float*)d_out;

    void *p0, *p1, *p2, *p3;
    cudaGetSymbolAddress(&p0, g_qkv);
    cudaGetSymbolAddress(&p1, g_attn);
    cudaGetSymbolAddress(&p2, g_wqkvt);
    cudaGetSymbolAddress(&p3, g_woutt);
    float* qkv   = (float*)p0;
    float* attn  = (float*)p1;
    float* wqkvt = (float*)p2;
    float* woutt = (float*)p3;

    const int M = B_ * L_;   // 4096

    cudaFuncSetAttribute(gemm_mma_kernel,
                         cudaFuncAttributeMaxDynamicSharedMemorySize, GM_SMEM);
    cudaFuncSetAttribute(flash_kernel,
                         cudaFuncAttributeMaxDynamicSharedMemorySize, FLASH_SMEM);

    // 0) Transpose weights so B operand is [N,K] row-major (.col layout)
    transpose_kernel<<<dim3(QKVN / 32, D_ / 32), dim3(32, 8)>>>(w_qkv, wqkvt, D_, QKVN);
    transpose_kernel<<<dim3(D_ / 32, D_ / 32), dim3(32, 8)>>>(w_out, woutt, D_, D_);

    // 1) QKV projection (tensor cores, tf32): [4096,1024] @ [1024,3072]
    gemm_mma_kernel<<<dim3(QKVN / 128, M / 128), 256, GM_SMEM>>>(
        x, wqkvt, b_qkv, qkv, M, QKVN, D_);

    // 2) Flash attention (fp32 SIMT)
    flash_kernel<<<dim3(L_ / 128, H_, B_), 256, FLASH_SMEM>>>(qkv, attn);

    // 3) Output projection (tensor cores, tf32): [4096,1024] @ [1024,1024]
    gemm_mma_kernel<<<dim3(D_ / 128, M / 128), 256, GM_SMEM>>>(
        attn, woutt, b_out, out, M, D_, D_);
}

// round 7
// speedup vs baseline: 2.3737x; 1.7764x over previous
#include <cuda_runtime.h>
#include <cstdint>
#include <math.h>

#define B_   2
#define L_   2048
#define D_   1024
#define H_   16
#define DK_  64
#define QKVN (3 * D_)
#define SOFTMAX_SCALE 0.125f   // 1/sqrt(64), exact power of two

// Scratch (allocation-free)
__device__ float g_qkv  [(size_t)B_ * L_ * QKVN];   // [B*L, 3072]
__device__ float g_attn [(size_t)B_ * L_ * D_];     // [B*L, 1024]
__device__ float g_wqkvt[(size_t)QKVN * D_];        // W_qkv^T  [3072,1024]
__device__ float g_woutt[(size_t)D_ * D_];          // W_out^T  [1024,1024]

// ---------------------------------------------------------------------------
// helpers
// ---------------------------------------------------------------------------
__device__ __forceinline__ uint32_t f2tf(float f) {   // fp32 -> tf32 (rna)
    uint32_t u;
    asm("cvt.rna.tf32.f32 %0, %1;" : "=r"(u) : "f"(f));
    return u;
}

// m16n8k8 tf32 HMMA (sm_80+ portable path)
__device__ __forceinline__ void mma_tf32(float c[4],
                                         uint32_t a0, uint32_t a1,
                                         uint32_t a2, uint32_t a3,
                                         uint32_t b0, uint32_t b1)
{
    asm volatile(
        "mma.sync.aligned.m16n8k8.row.col.f32.tf32.tf32.f32 "
        "{%0,%1,%2,%3}, {%4,%5,%6,%7}, {%8,%9}, {%0,%1,%2,%3};"
        : "+f"(c[0]), "+f"(c[1]), "+f"(c[2]), "+f"(c[3])
        : "r"(a0), "r"(a1), "r"(a2), "r"(a3), "r"(b0), "r"(b1));
}

// ---------------------------------------------------------------------------
// Transpose: src [R,C] -> dst [C,R]   (R,C multiples of 32)
// ---------------------------------------------------------------------------
__global__ void transpose_kernel(const float* __restrict__ src,
                                 float* __restrict__ dst, int R, int C)
{
    __shared__ float tile[32][33];
    int c0 = blockIdx.x * 32, r0 = blockIdx.y * 32;
    int x = threadIdx.x, y = threadIdx.y;
#pragma unroll
    for (int i = 0; i < 32; i += 8)
        tile[y + i][x] = src[(size_t)(r0 + y + i) * C + c0 + x];
    __syncthreads();
#pragma unroll
    for (int i = 0; i < 32; i += 8)
        dst[(size_t)(c0 + y + i) * R + r0 + x] = tile[x][y + i];
}

// ---------------------------------------------------------------------------
// Tensor-core GEMM (mma.sync tf32): C[M,N] = A[M,K] @ Bt[N,K]^T + bias[N]
// (unchanged from R4 — validated)
// ---------------------------------------------------------------------------
#define PAD    36
#define TILE_F (128 * PAD)
#define GM_SMEM (4 * TILE_F * 4)

__global__ __launch_bounds__(256) void gemm_mma_kernel(
    const float* __restrict__ A, const float* __restrict__ Bt,
    const float* __restrict__ bias, float* __restrict__ C,
    int M, int N, int K)
{
    extern __shared__ float smf[];
    float* As = smf;
    float* Bs = smf + 2 * TILE_F;

    const int t    = threadIdx.x;
    const int lane = t & 31;
    const int wid  = t >> 5;
    const int wm   = wid & 1;
    const int wn   = wid >> 1;
    const int m0   = blockIdx.y * 128;
    const int n0   = blockIdx.x * 128;
    const int g    = lane >> 2;
    const int tg   = lane & 3;

    float c[4][4][4];
#pragma unroll
    for (int i = 0; i < 4; i++)
#pragma unroll
        for (int j = 0; j < 4; j++)
#pragma unroll
            for (int x = 0; x < 4; x++) c[i][j][x] = 0.0f;

    const int nchunks = K >> 5;
    float4 ra[4], rb[4];

#pragma unroll
    for (int it = 0; it < 4; it++) {
        int li = t + 256 * it;
        int r  = li >> 3;
        int kq = (li & 7) << 2;
        ra[it] = *(const float4*)(A  + (size_t)(m0 + r) * K + kq);
        rb[it] = *(const float4*)(Bt + (size_t)(n0 + r) * K + kq);
    }
#pragma unroll
    for (int it = 0; it < 4; it++) {
        int li = t + 256 * it;
        int r  = li >> 3;
        int kq = (li & 7) << 2;
        *(uint4*)(As + r * PAD + kq) =
            make_uint4(f2tf(ra[it].x), f2tf(ra[it].y), f2tf(ra[it].z), f2tf(ra[it].w));
        *(uint4*)(Bs + r * PAD + kq) =
            make_uint4(f2tf(rb[it].x), f2tf(rb[it].y), f2tf(rb[it].z), f2tf(rb[it].w));
    }
    __syncthreads();

    for (int kt = 0; kt < nchunks; kt++) {
        const int buf = kt & 1;
        const bool more = (kt + 1 < nchunks);

        if (more) {
            const int k0 = (kt + 1) << 5;
#pragma unroll
            for (int it = 0; it < 4; it++) {
                int li = t + 256 * it;
                int r  = li >> 3;
                int kq = (li & 7) << 2;
                ra[it] = *(const float4*)(A  + (size_t)(m0 + r) * K + k0 + kq);
                rb[it] = *(const float4*)(Bt + (size_t)(n0 + r) * K + k0 + kq);
            }
        }

        const float* pa0 = As + buf * TILE_F + (wm * 64 + g) * PAD + tg;
        const float* pb0 = Bs + buf * TILE_F + (wn * 32 + g) * PAD + tg;
#pragma unroll
        for (int ks = 0; ks < 4; ks++) {
            const float* pa = pa0 + ks * 8;
            const float* pb = pb0 + ks * 8;
            uint32_t a[4][4], b[4][2];
#pragma unroll
            for (int i = 0; i < 4; i++) {
                a[i][0] = __float_as_uint(pa[(i * 16    ) * PAD    ]);
                a[i][1] = __float_as_uint(pa[(i * 16 + 8) * PAD    ]);
                a[i][2] = __float_as_uint(pa[(i * 16    ) * PAD + 4]);
                a[i][3] = __float_as_uint(pa[(i * 16 + 8) * PAD + 4]);
            }
#pragma unroll
            for (int j = 0; j < 4; j++) {
                b[j][0] = __float_as_uint(pb[(j * 8) * PAD    ]);
                b[j][1] = __float_as_uint(pb[(j * 8) * PAD + 4]);
            }
#pragma unroll
            for (int i = 0; i < 4; i++)
#pragma unroll
                for (int j = 0; j < 4; j++)
                    mma_tf32(c[i][j], a[i][0], a[i][1], a[i][2], a[i][3],
                             b[j][0], b[j][1]);
        }

        if (more) {
#pragma unroll
            for (int it = 0; it < 4; it++) {
                int li = t + 256 * it;
                int r  = li >> 3;
                int kq = (li & 7) << 2;
                *(uint4*)(As + (buf ^ 1) * TILE_F + r * PAD + kq) =
                    make_uint4(f2tf(ra[it].x), f2tf(ra[it].y),
                               f2tf(ra[it].z), f2tf(ra[it].w));
                *(uint4*)(Bs + (buf ^ 1) * TILE_F + r * PAD + kq) =
                    make_uint4(f2tf(rb[it].x), f2tf(rb[it].y),
                               f2tf(rb[it].z), f2tf(rb[it].w));
            }
        }
        __syncthreads();
    }

    const int ncol0 = n0 + wn * 32;
#pragma unroll
    for (int j = 0; j < 4; j++) {
        int cb = j * 8 + 2 * tg;
        float bv0 = bias[ncol0 + cb];
        float bv1 = bias[ncol0 + cb + 1];
#pragma unroll
        for (int i = 0; i < 4; i++) {
            int r = m0 + wm * 64 + i * 16 + g;
            float2 v0 = make_float2(c[i][j][0] + bv0, c[i][j][1] + bv1);
            float2 v1 = make_float2(c[i][j][2] + bv0, c[i][j][3] + bv1);
            *(float2*)(C + (size_t)r * N + ncol0 + cb)       = v0;
            *(float2*)(C + (size_t)(r + 8) * N + ncol0 + cb) = v1;
        }
    }
}

// ===========================================================================
// Tensor-core flash attention (mma.sync tf32)
// Block = (q-tile 128, head, batch), 256 threads = 8 warps, each warp owns
// 16 q-rows. kv-tile = 128. Q fragments register-resident (pre-scaled by
// 1/sqrt(dk)). K,V tiles in natural [kv, dk] smem layout (stride 68).
// P re-fragmented through a warp-private smem patch (stride 132).
// ===========================================================================
#define FM_KS   0
#define FM_VS   8704                       // 128*68
#define FM_PS   17408                      // 2*128*68
#define FM_PSTR 132
#define FM_SMEM ((FM_PS + 8 * 16 * FM_PSTR) * 4)   // 137216 B

__global__ __launch_bounds__(256) void flash_mma_kernel(
    const float* __restrict__ qkv, float* __restrict__ attn_out)
{
    extern __shared__ float smf[];
    float* Ks = smf + FM_KS;
    float* Vs = smf + FM_VS;

    const int t    = threadIdx.x;
    const int lane = t & 31;
    const int w    = t >> 5;
    const int g    = lane >> 2;     // 0..7
    const int tg   = lane & 3;      // 0..3
    const int q0   = blockIdx.x * 128;
    const int h    = blockIdx.y;
    const int b    = blockIdx.z;

    const float* basep = qkv + (size_t)b * L_ * QKVN + h * (3 * DK_);
    float* Pw = smf + FM_PS + w * 16 * FM_PSTR;   // warp-private P patch

    // ---- stage Q (pre-scaled, tf32) into Ks region, extract fragments ----
#pragma unroll
    for (int it = 0; it < 8; it++) {
        int li = t + 256 * it;
        int r  = li >> 4;
        int cq = (li & 15) << 2;
        float4 v = *(const float4*)(basep + (size_t)(q0 + r) * QKVN + cq);
        *(uint4*)(Ks + r * 68 + cq) = make_uint4(
            f2tf(v.x * SOFTMAX_SCALE), f2tf(v.y * SOFTMAX_SCALE),
            f2tf(v.z * SOFTMAX_SCALE), f2tf(v.w * SOFTMAX_SCALE));
    }
    __syncthreads();
    uint32_t aq[8][4];
#pragma unroll
    for (int ks = 0; ks < 8; ks++) {
        const float* q = Ks + (16 * w + g) * 68 + 8 * ks + tg;
        aq[ks][0] = __float_as_uint(q[0]);
        aq[ks][1] = __float_as_uint(q[8 * 68]);
        aq[ks][2] = __float_as_uint(q[4]);
        aq[ks][3] = __float_as_uint(q[8 * 68 + 4]);
    }

    float m0 = -1e30f, m1 = -1e30f, l0 = 0.0f, l1 = 0.0f;
    float o[8][4];
#pragma unroll
    for (int nt = 0; nt < 8; nt++)
#pragma unroll
        for (int x = 0; x < 4; x++) o[nt][x] = 0.0f;

    for (int kt = 0; kt < L_ / 128; kt++) {
        __syncthreads();                       // prev tile fully consumed
        const int kv0 = kt * 128;
#pragma unroll
        for (int it = 0; it < 8; it++) {
            int li = t + 256 * it;
            int r  = li >> 4;
            int cq = (li & 15) << 2;
            const float* src = basep + (size_t)(kv0 + r) * QKVN;
            float4 kv = *(const float4*)(src + DK_ + cq);
            *(uint4*)(Ks + r * 68 + cq) =
                make_uint4(f2tf(kv.x), f2tf(kv.y), f2tf(kv.z), f2tf(kv.w));
            float4 vv = *(const float4*)(src + 2 * DK_ + cq);
            *(uint4*)(Vs + r * 68 + cq) =
                make_uint4(f2tf(vv.x), f2tf(vv.y), f2tf(vv.z), f2tf(vv.w));
        }
        __syncthreads();

        // ---- S = (Q*scale) @ K^T : 16 n-tiles x 8 k-steps ----
        float s[16][4];
#pragma unroll
        for (int nt = 0; nt < 16; nt++)
#pragma unroll
            for (int x = 0; x < 4; x++) s[nt][x] = 0.0f;

#pragma unroll
        for (int ks = 0; ks < 8; ks++)
#pragma unroll
            for (int nt = 0; nt < 16; nt++) {
                const float* kb = Ks + (8 * nt + g) * 68 + 8 * ks + tg;
                uint32_t b0 = __float_as_uint(kb[0]);
                uint32_t b1 = __float_as_uint(kb[4]);
                mma_tf32(s[nt], aq[ks][0], aq[ks][1], aq[ks][2], aq[ks][3],
                         b0, b1);
            }

        // ---- online softmax (rows g and g+8 of this warp's 16) ----
        float rmax0 = -1e30f, rmax1 = -1e30f;
#pragma unroll
        for (int nt = 0; nt < 16; nt++) {
            rmax0 = fmaxf(rmax0, fmaxf(s[nt][0], s[nt][1]));
            rmax1 = fmaxf(rmax1, fmaxf(s[nt][2], s[nt][3]));
        }
        rmax0 = fmaxf(rmax0, __shfl_xor_sync(0xffffffffu, rmax0, 1));
        rmax0 = fmaxf(rmax0, __shfl_xor_sync(0xffffffffu, rmax0, 2));
        rmax1 = fmaxf(rmax1, __shfl_xor_sync(0xffffffffu, rmax1, 1));
        rmax1 = fmaxf(rmax1, __shfl_xor_sync(0xffffffffu, rmax1, 2));

        float mn0 = fmaxf(m0, rmax0), mn1 = fmaxf(m1, rmax1);
        float cf0 = __expf(m0 - mn0), cf1 = __expf(m1 - mn1);
        m0 = mn0; m1 = mn1;
        l0 *= cf0; l1 *= cf1;
#pragma unroll
        for (int nt = 0; nt < 8; nt++) {
            o[nt][0] *= cf0; o[nt][1] *= cf0;
            o[nt][2] *= cf1; o[nt][3] *= cf1;
        }

        float rs0 = 0.0f, rs1 = 0.0f;
#pragma unroll
        for (int nt = 0; nt < 16; nt++) {
            float p0 = __expf(s[nt][0] - mn0);
            float p1 = __expf(s[nt][1] - mn0);
            float p2 = __expf(s[nt][2] - mn1);
            float p3 = __expf(s[nt][3] - mn1);
            rs0 += p0 + p1;
            rs1 += p2 + p3;
            int cc = 8 * nt + 2 * tg;
            Pw[g * FM_PSTR + cc]           = __uint_as_float(f2tf(p0));
            Pw[g * FM_PSTR + cc + 1]       = __uint_as_float(f2tf(p1));
            Pw[(g + 8) * FM_PSTR + cc]     = __uint_as_float(f2tf(p2));
            Pw[(g + 8) * FM_PSTR + cc + 1] = __uint_as_float(f2tf(p3));
        }
        rs0 += __shfl_xor_sync(0xffffffffu, rs0, 1);
        rs0 += __shfl_xor_sync(0xffffffffu, rs0, 2);
        rs1 += __shfl_xor_sync(0xffffffffu, rs1, 1);
        rs1 += __shfl_xor_sync(0xffffffffu, rs1, 2);
        l0 += rs0; l1 += rs1;
        __syncwarp();

        // ---- O += P @ V : 16 k-steps (kv) x 8 n-tiles (dk) ----
#pragma unroll
        for (int ks = 0; ks < 16; ks++) {
            const float* pp = Pw + g * FM_PSTR + 8 * ks + tg;
            uint32_t a0 = __float_as_uint(pp[0]);
            uint32_t a1 = __float_as_uint(pp[8 * FM_PSTR]);
            uint32_t a2 = __float_as_uint(pp[4]);
            uint32_t a3 = __float_as_uint(pp[8 * FM_PSTR + 4]);
#pragma unroll
            for (int nt = 0; nt < 8; nt++) {
                uint32_t b0 = __float_as_uint(Vs[(8 * ks + tg) * 68 + 8 * nt + g]);
                uint32_t b1 = __float_as_uint(Vs[(8 * ks + tg + 4) * 68 + 8 * nt + g]);
                mma_tf32(o[nt], a0, a1, a2, a3, b0, b1);
            }
        }
        __syncwarp();
    }

    // ---- epilogue: normalize, write [B*L, D] head-merged ----
    float i0 = 1.0f / l0, i1 = 1.0f / l1;
    const size_t r0 = (size_t)b * L_ + q0 + 16 * w + g;
#pragma unroll
    for (int nt = 0; nt < 8; nt++) {
        int col = h * DK_ + 8 * nt + 2 * tg;
        *(float2*)(attn_out + r0 * D_ + col) =
            make_float2(o[nt][0] * i0, o[nt][1] * i0);
        *(float2*)(attn_out + (r0 + 8) * D_ + col) =
            make_float2(o[nt][2] * i1, o[nt][3] * i1);
    }
}

// ===========================================================================
// Launch
// ===========================================================================
extern "C" void kernel_launch(void* const* d_in, const int* in_sizes, int n_in,
                              void* d_out, int out_size)
{
    const float* x     = (const float*)d_in[0];
    const float* w_qkv = (const float*)d_in[1];
    const float* b_qkv = (const float*)d_in[2];
    const float* w_out = (const float*)d_in[3];
    const float* b_out = (const float*)d_in[4];
    float* out = (float*)d_out;

    void *p0, *p1, *p2, *p3;
    cudaGetSymbolAddress(&p0, g_qkv);
    cudaGetSymbolAddress(&p1, g_attn);
    cudaGetSymbolAddress(&p2, g_wqkvt);
    cudaGetSymbolAddress(&p3, g_woutt);
    float* qkv   = (float*)p0;
    float* attn  = (float*)p1;
    float* wqkvt = (float*)p2;
    float* woutt = (float*)p3;

    const int M = B_ * L_;   // 4096

    cudaFuncSetAttribute(gemm_mma_kernel,
                         cudaFuncAttributeMaxDynamicSharedMemorySize, GM_SMEM);
    cudaFuncSetAttribute(flash_mma_kernel,
                         cudaFuncAttributeMaxDynamicSharedMemorySize, FM_SMEM);

    // 0) Transpose weights so B operand is [N,K] row-major (.col layout)
    transpose_kernel<<<dim3(QKVN / 32, D_ / 32), dim3(32, 8)>>>(w_qkv, wqkvt, D_, QKVN);
    transpose_kernel<<<dim3(D_ / 32, D_ / 32), dim3(32, 8)>>>(w_out, woutt, D_, D_);

    // 1) QKV projection (tensor cores, tf32)
    gemm_mma_kernel<<<dim3(QKVN / 128, M / 128), 256, GM_SMEM>>>(
        x, wqkvt, b_qkv, qkv, M, QKVN, D_);

    // 2) Flash attention (tensor cores, tf32)
    flash_mma_kernel<<<dim3(L_ / 128, H_, B_), 256, FM_SMEM>>>(qkv, attn);

    // 3) Output projection (tensor cores, tf32)
    gemm_mma_kernel<<<dim3(D_ / 128, M / 128), 256, GM_SMEM>>>(
        attn, woutt, b_out, out, M, D_, D_);
}